// round 7
// baseline (speedup 1.0000x reference)
#include <cuda_runtime.h>
#include <math.h>
#include <stdint.h>

#define TT   1024
#define BB   512
#define DIN  128
#define HH   512
#define DOUT 128

#define NG   16      // batch groups
#define NS   8       // j slices
#define MB   32      // batch rows per group
#define JS   64      // hidden outputs per slice
#define CHUNK 128
#define NTHR 256

#define WP   644     // w_s row pitch (floats): 2576B = 16 mod 128 -> conflict-free
#define VP   132     // v_s chunk row pitch:     528B = 16 mod 128
#define VP2  260     // epilogue row pitch:     1040B = 16 mod 128

// Cross-CTA hidden-state exchange (double-buffered by step parity)
__device__ float    g_hbuf[2][BB][HH];      // 2 MB, L2-resident
__device__ unsigned g_flag[NG][NS][32];     // per-slice step counters, 128B apart

__global__ void zero_kernel() {
    int i = blockIdx.x * blockDim.x + threadIdx.x;
    int stride = gridDim.x * blockDim.x;
    float* p = &g_hbuf[0][0][0];
    for (int k = i; k < BB * HH; k += stride) p[k] = 0.f;
    unsigned* f = &g_flag[0][0][0];
    for (int k = i; k < NG * NS * 32; k += stride) f[k] = 0u;
}

__device__ __forceinline__ void lds_v2(uint64_t& a, uint64_t& b, uint32_t addr) {
    asm volatile("ld.shared.v2.u64 {%0,%1}, [%2];" : "=l"(a), "=l"(b) : "r"(addr));
}
#define FMA2(acc, w, h) \
    asm("fma.rn.f32x2 %0, %1, %2, %0;" : "+l"(acc) : "l"(w), "l"(h))

__device__ __forceinline__ float2 unpack2(uint64_t a) {
    float lo, hi;
    asm("mov.b64 {%0,%1}, %2;" : "=f"(lo), "=f"(hi) : "l"(a));
    return make_float2(lo, hi);
}

__global__ __launch_bounds__(NTHR, 1) void scan_kernel(
    const float* __restrict__ x,
    const float* __restrict__ Wx,
    const float* __restrict__ bx,
    const float* __restrict__ Wh,
    const float* __restrict__ bh,
    const float* __restrict__ Wy,
    const float* __restrict__ by,
    float* __restrict__ y)
{
    extern __shared__ float sm[];
    float* w_s = sm;                 // [JS][WP]
    float* v_s = sm + JS * WP;       // chunk bufs [2][MB][VP] / epi [MB][VP2]

    const int tid = threadIdx.x;
    const int g   = blockIdx.x >> 3;   // batch group
    const int s   = blockIdx.x & 7;    // j slice

    const int jp  = tid >> 3;          // 0..31 : j in {jp, jp+32}
    const int mq  = tid & 7;           // 0..7  : m in {mq, mq+8, mq+16, mq+24}
    const int rr  = tid >> 3;          // loader row 0..31
    const int cb  = tid & 7;           // loader col4 base 0..7

    // ---- load unified weight slice into smem (once); x-weights at col 512 ----
    const float4* Wh4 = reinterpret_cast<const float4*>(Wh);
    const float4* Wx4 = reinterpret_cast<const float4*>(Wx);
    for (int i = tid; i < JS * (HH / 4); i += NTHR) {
        int jl = i >> 7, c4 = i & 127;
        float4 w = Wh4[(size_t)(s * JS + jl) * (HH / 4) + c4];
        *reinterpret_cast<float4*>(&w_s[jl * WP + c4 * 4]) = w;
    }
    for (int i = tid; i < JS * (DIN / 4); i += NTHR) {
        int jl = i >> 5, c4 = i & 31;
        float4 w = Wx4[(size_t)(s * JS + jl) * (DIN / 4) + c4];
        *reinterpret_cast<float4*>(&w_s[jl * WP + HH + c4 * 4]) = w;
    }
    const int jg0 = s * JS + jp, jg1 = jg0 + 32;
    const float bias0 = bx[jg0] + bh[jg0];
    const float bias1 = bx[jg1] + bh[jg1];
    __syncthreads();

    const uint32_t w_sh = (uint32_t)__cvta_generic_to_shared(w_s);
    const uint32_t v_sh = (uint32_t)__cvta_generic_to_shared(v_s);

    const float* __restrict__ xrow = &x[(size_t)(g * MB + rr) * TT * DIN];
    const float* __restrict__ hrow0 = &g_hbuf[0][g * MB + rr][0];
    const float* __restrict__ hrow1 = &g_hbuf[1][g * MB + rr][0];

    float4 pre[4];
    // prefetch x chunk for t=0
    #pragma unroll
    for (int qq = 0; qq < 4; ++qq)
        pre[qq] = __ldg(reinterpret_cast<const float4*>(xrow + (cb + 8 * qq) * 4));

    int p = 0;

    for (int t = 0; t < TT; ++t) {
        uint64_t accs[2][2][4];
        #pragma unroll
        for (int bk = 0; bk < 2; ++bk)
            #pragma unroll
            for (int jj = 0; jj < 2; ++jj)
                #pragma unroll
                for (int i = 0; i < 4; ++i) accs[bk][jj][i] = 0ull;

        const float* __restrict__ hr = p ? hrow1 : hrow0;

        // ---- stage x chunk (prefetched last step) into buf0 ----
        {
            float* vrow = &v_s[(0 * MB + rr) * VP];
            #pragma unroll
            for (int qq = 0; qq < 4; ++qq)
                *reinterpret_cast<float4*>(vrow + (cb + 8 * qq) * 4) = pre[qq];
        }
        __syncthreads();
        // LDG h chunk 0 (in flight under x compute)
        #pragma unroll
        for (int qq = 0; qq < 4; ++qq)
            pre[qq] = __ldcg(reinterpret_cast<const float4*>(hr + (cb + 8 * qq) * 4));

        // ---- compute macro: one 128-wide K chunk ----
        #define COMPUTE_CHUNK(KOFF, VB)                                          \
        do {                                                                     \
            const uint32_t wa0 = w_sh + (uint32_t)((jp * WP + (KOFF)) * 4);      \
            const uint32_t wa1 = wa0 + (uint32_t)(32 * WP * 4);                  \
            const uint32_t hb  = v_sh + (uint32_t)(((VB) * MB + mq) * VP * 4);   \
            _Pragma("unroll")                                                    \
            for (int q = 0; q < 32; ++q) {                                       \
                const int bk = q & 1;                                            \
                uint64_t w0l, w0h, w1l, w1h;                                     \
                lds_v2(w0l, w0h, wa0 + q * 16);                                  \
                lds_v2(w1l, w1h, wa1 + q * 16);                                  \
                _Pragma("unroll")                                                \
                for (int i = 0; i < 4; ++i) {                                    \
                    uint64_t hl, hh;                                             \
                    lds_v2(hl, hh, hb + (uint32_t)(i * 8 * VP * 4) + q * 16);    \
                    FMA2(accs[bk][0][i], w0l, hl);                               \
                    FMA2(accs[bk][0][i], w0h, hh);                               \
                    FMA2(accs[bk][1][i], w1l, hl);                               \
                    FMA2(accs[bk][1][i], w1h, hh);                               \
                }                                                                \
            }                                                                    \
        } while (0)

        // x chunk uses weight cols [512,640), staged in buf 0
        COMPUTE_CHUNK(HH, 0);

        #pragma unroll
        for (int c = 0; c < 4; ++c) {
            const int vb = (c + 1) & 1;   // h0->1, h1->0, h2->1, h3->0
            {
                float* vrow = &v_s[(vb * MB + rr) * VP];
                #pragma unroll
                for (int qq = 0; qq < 4; ++qq)
                    *reinterpret_cast<float4*>(vrow + (cb + 8 * qq) * 4) = pre[qq];
            }
            __syncthreads();
            if (c < 3) {
                #pragma unroll
                for (int qq = 0; qq < 4; ++qq)
                    pre[qq] = __ldcg(reinterpret_cast<const float4*>(
                                  hr + (c + 1) * CHUNK + (cb + 8 * qq) * 4));
            } else {
                const int tn = (t + 1 < TT) ? t + 1 : 0;   // prefetch x for next step
                const float* xr2 = xrow + (size_t)tn * DIN;
                #pragma unroll
                for (int qq = 0; qq < 4; ++qq)
                    pre[qq] = __ldg(reinterpret_cast<const float4*>(
                                  xr2 + (cb + 8 * qq) * 4));
            }
            COMPUTE_CHUNK(c * CHUNK, vb);
        }
        #undef COMPUTE_CHUNK

        // ---- finalize: merge banks, bias, tanh, publish ----
        const int q2 = p ^ 1;
        #pragma unroll
        for (int jj = 0; jj < 2; ++jj) {
            const float bb = jj ? bias1 : bias0;
            const int   jc = jj ? jg1 : jg0;
            #pragma unroll
            for (int i = 0; i < 4; ++i) {
                float2 vA = unpack2(accs[0][jj][i]);
                float2 vB = unpack2(accs[1][jj][i]);
                float hval = tanhf(vA.x + vA.y + vB.x + vB.y + bb);
                g_hbuf[q2][g * MB + mq + 8 * i][jc] = hval;
            }
        }

        // ---- cheap cross-CTA step barrier ----
        __syncthreads();                      // all h-stores issued (CTA-ordered)
        if (tid == 0) {
            // cumulative release: publishes every thread's h-stores
            asm volatile("st.release.gpu.global.u32 [%0], %1;"
                         :: "l"(&g_flag[g][s][0]), "r"((unsigned)(t + 1))
                         : "memory");
        }
        if (tid < NS) {
            const unsigned tgt = (unsigned)(t + 1);
            unsigned v;
            do {
                asm volatile("ld.acquire.gpu.global.u32 %0, [%1];"
                             : "=r"(v) : "l"(&g_flag[g][tid][0]));
            } while (v < tgt);
        }
        __syncthreads();
        p ^= 1;
    }

    // ---- epilogue: y[b, o] = by[o] + sum_k Wy[o,k]*h_T[b,k]; h_T in g_hbuf[0]
    const int oc = tid & 15;          // 0..15
    const int me = tid >> 4;          // 0..15? no: 256/16 = 16 rows... need 32
    // NOTE: 256 threads: oc 0..15 (o), me 0..15 — but MB=32 rows.
    // Use two row-passes: each thread handles rows me and me+16.
    const int o  = s * 16 + oc;
    const ulonglong2* Wy2 = reinterpret_cast<const ulonglong2*>(Wy);

    #pragma unroll
    for (int half = 0; half < 2; ++half) {
        const int mrow = me + 16 * half;
        uint64_t ya = 0ull;
        #pragma unroll
        for (int c = 0; c < 2; ++c) {
            __syncthreads();
            // stage 256-float chunk of h rows [0..15]+16*half into v_s
            #pragma unroll
            for (int qq = 0; qq < 4; ++qq) {
                int c4 = oc + 16 * qq;    // 0..63 float4
                float4 vv = __ldcg(reinterpret_cast<const float4*>(
                                &g_hbuf[0][g * MB + mrow][c * 256 + c4 * 4]));
                *reinterpret_cast<float4*>(&v_s[me * VP2 + c4 * 4]) = vv;
            }
            __syncthreads();
            const uint32_t hb = v_sh + (uint32_t)(me * VP2 * 4);
            #pragma unroll 8
            for (int k4 = 0; k4 < 64; ++k4) {
                uint64_t hl, hh;
                lds_v2(hl, hh, hb + k4 * 16);
                ulonglong2 w = __ldg(&Wy2[(size_t)o * 128 + c * 64 + k4]);
                FMA2(ya, w.x, hl);
                FMA2(ya, w.y, hh);
            }
        }
        float2 a = unpack2(ya);
        y[(size_t)(g * MB + mrow) * DOUT + o] = by[o] + a.x + a.y;
    }
}

extern "C" void kernel_launch(void* const* d_in, const int* in_sizes, int n_in,
                              void* d_out, int out_size) {
    const float* x  = (const float*)d_in[0];
    const float* Wx = (const float*)d_in[1];
    const float* bx = (const float*)d_in[2];
    const float* Wh = (const float*)d_in[3];
    const float* bh = (const float*)d_in[4];
    const float* Wy = (const float*)d_in[5];
    const float* by = (const float*)d_in[6];
    float* y = (float*)d_out;

    int vfloats = 2 * MB * VP;                 // 8448
    if (MB * VP2 > vfloats) vfloats = MB * VP2;
    const int smem_bytes = (JS * WP + vfloats) * (int)sizeof(float);
    cudaFuncSetAttribute(scan_kernel,
                         cudaFuncAttributeMaxDynamicSharedMemorySize, smem_bytes);

    zero_kernel<<<256, 256>>>();
    scan_kernel<<<NG * NS, NTHR, smem_bytes>>>(x, Wx, bx, Wh, bh, Wy, by, y);
}

// round 8
// speedup vs baseline: 1.4099x; 1.4099x over previous
#include <cuda_runtime.h>
#include <math.h>
#include <stdint.h>

#define TT   1024
#define BB   512
#define DIN  128
#define HH   512
#define DOUT 128

#define NG   16
#define NS   8
#define MB   32
#define JS   64
#define NTHR 256

// smem byte offsets
#define WPB   528            // w row pitch bytes (66 u64)
#define VPB   272            // v row pitch bytes (34 u64)
#define VBUF  17408          // one v buffer: 64 rows * 272
#define W_OFF 0              // 320*528 = 168960
#define V_OFF 168960         // 2*17408 = 34816
#define R_OFF 203776         // red: 3*32*66*4 = 25344
#define B_OFF 229120         // bias: 64*4
#define SMEM_TOTAL 229376

// k-pair-packed weights: W2[kq][j] = {w[j][2kq], w[j][2kq+1]}; kq<256 -> Wh, 256..319 -> Wx
__device__ unsigned long long g_W2[320 * 512];
// hidden state, k-pair-packed: g_h2[p][kq*512 + b] = {h[2kq][b], h[2kq+1][b]}
__device__ unsigned long long g_h2[2][256 * 512];
__device__ unsigned g_flag[NG][NS][32];

__global__ void prep_kernel(const float* __restrict__ Wh,
                            const float* __restrict__ Wx) {
    int i = blockIdx.x * blockDim.x + threadIdx.x;
    int stride = gridDim.x * blockDim.x;
    for (int idx = i; idx < 320 * 512; idx += stride) {
        int kq = idx >> 9;
        int j  = idx & 511;
        unsigned long long v;
        if (kq < 256)
            v = *reinterpret_cast<const unsigned long long*>(&Wh[j * HH + 2 * kq]);
        else
            v = *reinterpret_cast<const unsigned long long*>(&Wx[j * DIN + 2 * (kq - 256)]);
        g_W2[idx] = v;
    }
}

__global__ void zero_kernel() {
    int i = blockIdx.x * blockDim.x + threadIdx.x;
    int stride = gridDim.x * blockDim.x;
    unsigned long long* p = &g_h2[0][0];
    for (int k = i; k < 256 * 512; k += stride) p[k] = 0ull;
    unsigned* f = &g_flag[0][0][0];
    for (int k = i; k < NG * NS * 32; k += stride) f[k] = 0u;
}

__device__ __forceinline__ void lds_v2(uint64_t& a, uint64_t& b, uint32_t addr) {
    asm volatile("ld.shared.v2.u64 {%0,%1}, [%2];" : "=l"(a), "=l"(b) : "r"(addr));
}
#define FMA2(acc, w, h) \
    asm("fma.rn.f32x2 %0, %1, %2, %0;" : "+l"(acc) : "l"(w), "l"(h))

__device__ __forceinline__ float2 unpack2(uint64_t a) {
    float lo, hi;
    asm("mov.b64 {%0,%1}, %2;" : "=f"(lo), "=f"(hi) : "l"(a));
    return make_float2(lo, hi);
}

__global__ __launch_bounds__(NTHR, 1) void scan_kernel(
    const float* __restrict__ x,
    const float* __restrict__ bx,
    const float* __restrict__ bh,
    const float* __restrict__ Wy,
    const float* __restrict__ by,
    float* __restrict__ y)
{
    extern __shared__ char smem[];
    const uint32_t sb = (uint32_t)__cvta_generic_to_shared(smem);
    float* red    = reinterpret_cast<float*>(smem + R_OFF);
    float* bias_s = reinterpret_cast<float*>(smem + B_OFF);

    const int tid = threadIdx.x;
    const int g   = blockIdx.x >> 3;
    const int s   = blockIdx.x & 7;

    // compute decode: quarter z, 8 j-threads, 8 m-threads
    const int z  = tid >> 6;          // 0..3 (k-split quarter)
    const int jt = tid & 7;           // j pairs at cols {2jt+16p}, p=0..3
    const int mt = (tid >> 3) & 7;    // m = 4*mt + mm

    // staging decode
    const int sr = tid >> 4;          // 0..15
    const int sc = tid & 15;          // 0..15 (16B units)
    // x staging decode
    const int xb  = tid & 31;
    const int xdc = tid >> 5;         // 0..7

    // ---- load weight slice into smem in CHUNK order (x rows first) ----
    for (int i = tid; i < 320 * 64; i += NTHR) {
        int wr = i >> 6, jl = i & 63;
        int w2row = (wr < 64) ? (256 + wr) : (wr - 64);
        reinterpret_cast<unsigned long long*>(smem + W_OFF)[wr * 66 + jl] =
            g_W2[(size_t)w2row * 512 + s * JS + jl];
    }
    if (tid < 64) bias_s[tid] = bx[s * JS + tid] + bh[s * JS + tid];

    const float* __restrict__ xrow = &x[(size_t)(g * MB + xb) * TT * DIN];

    float4 pre[4];
    // ---- prologue: stage x(t=0) into buf 0 ----
    #pragma unroll
    for (int it = 0; it < 4; ++it)
        pre[it] = __ldg(reinterpret_cast<const float4*>(xrow + (xdc + 8 * it) * 4));
    #pragma unroll
    for (int it = 0; it < 4; ++it) {
        int dq = xdc + 8 * it;
        char* b0 = smem + V_OFF + (2 * dq) * VPB + xb * 8;
        *reinterpret_cast<float2*>(b0)       = make_float2(pre[it].x, pre[it].y);
        *reinterpret_cast<float2*>(b0 + VPB) = make_float2(pre[it].z, pre[it].w);
    }
    __syncthreads();

    #define LDG_H(P, CH64)                                                       \
        do {                                                                     \
            const unsigned long long* hs = &g_h2[(P)][0];                        \
            _Pragma("unroll")                                                    \
            for (int it = 0; it < 4; ++it)                                       \
                pre[it] = __ldcg(reinterpret_cast<const float4*>(                \
                    hs + (size_t)((CH64) + sr + 16 * it) * 512 + g * MB + sc * 2)); \
        } while (0)

    #define STS_H(VB)                                                            \
        do {                                                                     \
            _Pragma("unroll")                                                    \
            for (int it = 0; it < 4; ++it)                                       \
                *reinterpret_cast<float4*>(smem + V_OFF + (VB) * VBUF +          \
                    (sr + 16 * it) * VPB + sc * 16) = pre[it];                   \
        } while (0)

    #define COMPUTE(C, VB)                                                       \
        do {                                                                     \
            uint32_t wa = sb + (uint32_t)(W_OFF + ((C) * 64 + z * 16) * WPB + jt * 16); \
            uint32_t va = sb + (uint32_t)(V_OFF + (VB) * VBUF + (z * 16) * VPB + mt * 32); \
            _Pragma("unroll")                                                    \
            for (int qq = 0; qq < 16; ++qq) {                                    \
                uint64_t w00,w01,w10,w11,w20,w21,w30,w31,h0,h1,h2,h3;            \
                lds_v2(w00,w01, wa);                                             \
                lds_v2(w10,w11, wa + 128);                                       \
                lds_v2(w20,w21, wa + 256);                                       \
                lds_v2(w30,w31, wa + 384);                                       \
                lds_v2(h0,h1, va);                                               \
                lds_v2(h2,h3, va + 16);                                          \
                FMA2(acc[ 0],w00,h0); FMA2(acc[ 1],w00,h1); FMA2(acc[ 2],w00,h2); FMA2(acc[ 3],w00,h3); \
                FMA2(acc[ 4],w01,h0); FMA2(acc[ 5],w01,h1); FMA2(acc[ 6],w01,h2); FMA2(acc[ 7],w01,h3); \
                FMA2(acc[ 8],w10,h0); FMA2(acc[ 9],w10,h1); FMA2(acc[10],w10,h2); FMA2(acc[11],w10,h3); \
                FMA2(acc[12],w11,h0); FMA2(acc[13],w11,h1); FMA2(acc[14],w11,h2); FMA2(acc[15],w11,h3); \
                FMA2(acc[16],w20,h0); FMA2(acc[17],w20,h1); FMA2(acc[18],w20,h2); FMA2(acc[19],w20,h3); \
                FMA2(acc[20],w21,h0); FMA2(acc[21],w21,h1); FMA2(acc[22],w21,h2); FMA2(acc[23],w21,h3); \
                FMA2(acc[24],w30,h0); FMA2(acc[25],w30,h1); FMA2(acc[26],w30,h2); FMA2(acc[27],w30,h3); \
                FMA2(acc[28],w31,h0); FMA2(acc[29],w31,h1); FMA2(acc[30],w31,h2); FMA2(acc[31],w31,h3); \
                wa += WPB; va += VPB;                                            \
            }                                                                    \
        } while (0)

    int p = 0;
    for (int t = 0; t < TT; ++t) {
        uint64_t acc[32];
        #pragma unroll
        for (int i = 0; i < 32; ++i) acc[i] = 0ull;

        LDG_H(p, 0);          // h chunk 1
        COMPUTE(0, p);        // x chunk (staged in buf p)
        STS_H(p ^ 1);
        __syncthreads();

        LDG_H(p, 64);
        COMPUTE(1, p ^ 1);
        STS_H(p);
        __syncthreads();

        LDG_H(p, 128);
        COMPUTE(2, p);
        STS_H(p ^ 1);
        __syncthreads();

        LDG_H(p, 192);
        COMPUTE(3, p ^ 1);
        STS_H(p);
        __syncthreads();

        // prefetch x(t+1), compute last chunk, stage x into buf p^1
        {
            const int tn = (t + 1 < TT) ? t + 1 : t;
            const float* xr = xrow + (size_t)tn * DIN;
            #pragma unroll
            for (int it = 0; it < 4; ++it)
                pre[it] = __ldg(reinterpret_cast<const float4*>(xr + (xdc + 8 * it) * 4));
        }
        COMPUTE(4, p);
        #pragma unroll
        for (int it = 0; it < 4; ++it) {
            int dq = xdc + 8 * it;
            char* b0 = smem + V_OFF + (p ^ 1) * VBUF + (2 * dq) * VPB + xb * 8;
            *reinterpret_cast<float2*>(b0)       = make_float2(pre[it].x, pre[it].y);
            *reinterpret_cast<float2*>(b0 + VPB) = make_float2(pre[it].z, pre[it].w);
        }

        // ---- reduction: quarters 1-3 dump partials; quarter 0 finalizes ----
        if (z != 0) {
            #pragma unroll
            for (int pp = 0; pp < 4; ++pp)
                #pragma unroll
                for (int jj = 0; jj < 2; ++jj)
                    #pragma unroll
                    for (int mm = 0; mm < 4; ++mm) {
                        float2 v = unpack2(acc[pp * 8 + jj * 4 + mm]);
                        int j = 2 * jt + 16 * pp + jj;
                        int m = 4 * mt + mm;
                        red[((z - 1) * 32 + m) * 66 + j] = v.x + v.y;
                    }
        }
        __syncthreads();
        if (z == 0) {
            float* hdst = reinterpret_cast<float*>(&g_h2[p ^ 1][0]);
            #pragma unroll
            for (int pp = 0; pp < 4; ++pp)
                #pragma unroll
                for (int jj = 0; jj < 2; ++jj)
                    #pragma unroll
                    for (int mm = 0; mm < 4; ++mm) {
                        float2 v = unpack2(acc[pp * 8 + jj * 4 + mm]);
                        int j = 2 * jt + 16 * pp + jj;
                        int m = 4 * mt + mm;
                        float sum = v.x + v.y
                                  + red[(m) * 66 + j]
                                  + red[(32 + m) * 66 + j]
                                  + red[(64 + m) * 66 + j]
                                  + bias_s[j];
                        float hv = tanhf(sum);
                        size_t off = ((size_t)(32 * s + jt + 8 * pp) * 512
                                      + g * MB + m) * 2 + jj;
                        __stcg(&hdst[off], hv);
                    }
        }
        __syncthreads();
        if (tid == 0) {
            asm volatile("fence.acq_rel.gpu;" ::: "memory");
            asm volatile("st.release.gpu.global.u32 [%0], %1;"
                         :: "l"(&g_flag[g][s][0]), "r"((unsigned)(t + 1))
                         : "memory");
        }
        if (tid < NS) {
            const unsigned tgt = (unsigned)(t + 1);
            unsigned v;
            do {
                asm volatile("ld.acquire.gpu.global.u32 %0, [%1];"
                             : "=r"(v) : "l"(&g_flag[g][tid][0]));
            } while (v < tgt);
        }
        __syncthreads();
        p ^= 1;
    }

    // ---- epilogue: y = h_T @ Wy^T + by ; h_T packed in g_h2[0] ----
    const int o  = s * 16 + (tid & 15);
    const int me = tid >> 4;            // 0..15
    const unsigned long long* hfin = &g_h2[0][0];
    const unsigned long long* Wy2  = reinterpret_cast<const unsigned long long*>(Wy);
    uint64_t ya0 = 0ull, ya1 = 0ull;

    #pragma unroll
    for (int half = 0; half < 2; ++half) {
        __syncthreads();
        // stage 128 kq rows of this k-half into v region
        #pragma unroll
        for (int it = 0; it < 8; ++it) {
            int r = sr + 16 * it;
            float4 vv = __ldcg(reinterpret_cast<const float4*>(
                hfin + (size_t)(half * 128 + r) * 512 + g * MB + sc * 2));
            *reinterpret_cast<float4*>(smem + V_OFF + r * VPB + sc * 16) = vv;
        }
        __syncthreads();
        #pragma unroll 8
        for (int kq = 0; kq < 128; ++kq) {
            uint64_t h0 = *reinterpret_cast<uint64_t*>(
                smem + V_OFF + kq * VPB + me * 8);
            uint64_t h1 = *reinterpret_cast<uint64_t*>(
                smem + V_OFF + kq * VPB + (me + 16) * 8);
            unsigned long long wv = __ldg(&Wy2[(size_t)o * 256 + half * 128 + kq]);
            FMA2(ya0, wv, h0);
            FMA2(ya1, wv, h1);
        }
    }
    {
        float2 a0 = unpack2(ya0), a1 = unpack2(ya1);
        y[(size_t)(g * MB + me) * DOUT + o]      = by[o] + a0.x + a0.y;
        y[(size_t)(g * MB + me + 16) * DOUT + o] = by[o] + a1.x + a1.y;
    }
}

extern "C" void kernel_launch(void* const* d_in, const int* in_sizes, int n_in,
                              void* d_out, int out_size) {
    const float* x  = (const float*)d_in[0];
    const float* Wx = (const float*)d_in[1];
    const float* bx = (const float*)d_in[2];
    const float* Wh = (const float*)d_in[3];
    const float* bh = (const float*)d_in[4];
    const float* Wy = (const float*)d_in[5];
    const float* by = (const float*)d_in[6];
    float* y = (float*)d_out;

    cudaFuncSetAttribute(scan_kernel,
                         cudaFuncAttributeMaxDynamicSharedMemorySize, SMEM_TOTAL);

    prep_kernel<<<256, 256>>>(Wh, Wx);
    zero_kernel<<<256, 256>>>();
    scan_kernel<<<NG * NS, NTHR, SMEM_TOTAL>>>(x, bx, bh, Wy, by, y);
}